// round 16
// baseline (speedup 1.0000x reference)
#include <cuda_runtime.h>
#include <cuda_bf16.h>
#include <cstdint>

// ---------------- problem-size constants (fixed by the reference) ----------
#define NNODES   50000
#define NPAD     50048                  // padded to multiple of 128
#define NEDGES   800000
#define ETOT     (NNODES + NEDGES)      // 850000 (edges + self loops)
#define SCAN_BS  512

// ---------------- device scratch (no allocations allowed) ------------------
// ONLY referenced from device code (host-side use of a __device__ symbol as a
// kernel arg silently reads the host shadow via ATS -> zero output).
__device__ float g_l0[(size_t)NPAD * 256];   // [x@W0^T | x@linW0^T]
__device__ float g_l1[(size_t)NPAD * 64];    // [h@W1^T | h@linW1^T]
__device__ __nv_bfloat16 g_hh[(size_t)NPAD * 128];
__device__ __nv_bfloat16 g_hl[(size_t)NPAD * 128];
__device__ float g_as0[NNODES * 4];
__device__ float g_ad0[NNODES * 4];
__device__ float g_as1[NNODES];
__device__ float g_ad1[NNODES];
__device__ int   g_deg[NNODES + 64];
__device__ int   g_rowtmp[NNODES + 64];
__device__ int   g_rowptr[NNODES + 64];
__device__ int   g_cursor[NNODES + 64];
__device__ int   g_csr_src[ETOT + 64];
__device__ int   g_bsum[SCAN_BS];
__device__ __nv_bfloat16 g_B0h[256 * 128];
__device__ __nv_bfloat16 g_B0l[256 * 128];
__device__ __nv_bfloat16 g_B1h[64 * 128];
__device__ __nv_bfloat16 g_B1l[64 * 128];

// ---------------- helpers ---------------------------------------------------
__device__ __forceinline__ uint32_t smem_u32(const void* p) {
    uint32_t a;
    asm("{ .reg .u64 t; cvta.to.shared.u64 t, %1; cvt.u32.u64 %0, t; }" : "=r"(a) : "l"(p));
    return a;
}
__device__ __forceinline__ void ldsm_x4(uint32_t* r, uint32_t addr) {
    asm volatile("ldmatrix.sync.aligned.m8n8.x4.shared.b16 {%0,%1,%2,%3}, [%4];"
                 : "=r"(r[0]), "=r"(r[1]), "=r"(r[2]), "=r"(r[3]) : "r"(addr));
}
__device__ __forceinline__ void ldsm_x2(uint32_t* r, uint32_t addr) {
    asm volatile("ldmatrix.sync.aligned.m8n8.x2.shared.b16 {%0,%1}, [%2];"
                 : "=r"(r[0]), "=r"(r[1]) : "r"(addr));
}
__device__ __forceinline__ void mma_bf16(float* d, const uint32_t* a, const uint32_t* b) {
    asm volatile(
        "mma.sync.aligned.m16n8k16.row.col.f32.bf16.bf16.f32 "
        "{%0,%1,%2,%3}, {%4,%5,%6,%7}, {%8,%9}, {%0,%1,%2,%3};"
        : "+f"(d[0]), "+f"(d[1]), "+f"(d[2]), "+f"(d[3])
        : "r"(a[0]), "r"(a[1]), "r"(a[2]), "r"(a[3]), "r"(b[0]), "r"(b[1]));
}

// ---------------- setup: weight split (default stream, feeds GEMM0) ---------
__global__ void k_setupW(const float* __restrict__ W0, const float* __restrict__ lW0,
                         const float* __restrict__ W1, const float* __restrict__ lW1) {
    int i = blockIdx.x * blockDim.x + threadIdx.x;
    if (i < 128 * 128) {
        float v = W0[i];
        __nv_bfloat16 h = __float2bfloat16_rn(v);
        g_B0h[i] = h; g_B0l[i] = __float2bfloat16_rn(v - __bfloat162float(h));
        v = lW0[i];
        h = __float2bfloat16_rn(v);
        g_B0h[128 * 128 + i] = h; g_B0l[128 * 128 + i] = __float2bfloat16_rn(v - __bfloat162float(h));
    }
    if (i < 32 * 128) {
        float v = W1[i];
        __nv_bfloat16 h = __float2bfloat16_rn(v);
        g_B1h[i] = h; g_B1l[i] = __float2bfloat16_rn(v - __bfloat162float(h));
        v = lW1[i];
        h = __float2bfloat16_rn(v);
        g_B1h[32 * 128 + i] = h; g_B1l[32 * 128 + i] = __float2bfloat16_rn(v - __bfloat162float(h));
    }
}

// ---------------- CSR build (stream s2) --------------------------------------
__global__ void k_zero_deg(int n) {
    int i = blockIdx.x * blockDim.x + threadIdx.x;
    if (i < n) g_deg[i] = 0;
}
__global__ void k_hist(const int* __restrict__ ei, int e, int etot) {
    int k = blockIdx.x * blockDim.x + threadIdx.x;
    if (k >= etot) return;
    int dst = (k < e) ? ei[e + k] : (k - e);
    atomicAdd(&g_deg[dst], 1);
}
__global__ void k_scan1(int n) {
    __shared__ int sh[SCAN_BS];
    int t = threadIdx.x;
    int i = blockIdx.x * SCAN_BS + t;
    int v = (i < n) ? g_deg[i] : 0;
    sh[t] = v;
    __syncthreads();
    for (int o = 1; o < SCAN_BS; o <<= 1) {
        int x = (t >= o) ? sh[t - o] : 0;
        __syncthreads();
        sh[t] += x;
        __syncthreads();
    }
    if (i < n) g_rowtmp[i] = sh[t];
    if (t == SCAN_BS - 1) g_bsum[blockIdx.x] = sh[t];
}
// merged scan2+scan3: block b (256 thr) lies fully in bsum region b>>1, so it
// block-reduces g_bsum[0..b>>1) and applies the exclusive region offset.
__global__ void k_scan23(int n) {
    __shared__ int red[256];
    int t = threadIdx.x, b = blockIdx.x;
    int region = b >> 1;                    // 512-wide regions, 256-wide blocks
    red[t] = (t < region) ? g_bsum[t] : 0;  // region <= 98 < 256
    __syncthreads();
    for (int o = 128; o; o >>= 1) {
        if (t < o) red[t] += red[t + o];
        __syncthreads();
    }
    int pre = red[0];
    int i = b * 256 + t;
    if (i < n) {
        int incl = g_rowtmp[i] + pre;
        g_rowptr[i + 1] = incl;
        g_cursor[i] = incl - g_deg[i];
        if (i == 0) g_rowptr[0] = 0;
    }
}
__global__ void k_scatter(const int* __restrict__ ei, int e, int etot) {
    int k = blockIdx.x * blockDim.x + threadIdx.x;
    if (k >= etot) return;
    int src, dst;
    if (k < e) { src = ei[k]; dst = ei[e + k]; }
    else       { src = dst = k - e; }
    int pos = atomicAdd(&g_cursor[dst], 1);
    g_csr_src[pos] = src;
}

// ---------------- HMMA GEMM + fused attention logits -------------------------
// Single launch per layer. A staged once; B processed in NSLAB slabs of NN
// columns inside the kernel (acc registers reused).
// fp32 via 3-product bf16 split (Ah*Bh + Al*Bh + Ah*Bl), fp32 reg accum.
// L=0: A = x (fp32, split in staging), B=g_B0h/l, C=g_l0, 2 slabs of 128.
// L=1: A = g_hh/g_hl, B=g_B1h/l, C=g_l1, 1 slab of 64.
// Slab 0 covers the h-columns: fused a_src/a_dst logits in its epilogue.
template <int L>
__global__ void __launch_bounds__(256) k_mma(
    const float* __restrict__ xsrc,
    const float* __restrict__ attS, const float* __restrict__ attD, int M)
{
    constexpr int NSLAB = (L == 0) ? 2 : 1;
    constexpr int NN  = (L == 0) ? 128 : 64;   // cols per slab
    constexpr int CS  = (L == 0) ? 256 : 64;   // C row stride
    constexpr int WNN = (NN == 128) ? 4 : 2;   // warps along n
    constexpr int WMN = 8 / WNN;               // warps along m
    constexpr int WARP_M = 128 / WMN;          // 64 or 32
    constexpr int MI = WARP_M / 16;            // 4 or 2
    constexpr int NI = 4;                      // WARP_N = 32 (one head)
    constexpr int PB = 272;                    // pitch bytes (17*16B -> conflict-free)
    constexpr int SM_AHI = 0;
    constexpr int SM_ALO = 128 * PB;
    constexpr int SM_BHI = 2 * 128 * PB;
    constexpr int SM_BLO = SM_BHI + NN * PB;

    const __nv_bfloat16* __restrict__ Bh = (L == 0) ? g_B0h : g_B1h;
    const __nv_bfloat16* __restrict__ Bl = (L == 0) ? g_B0l : g_B1l;
    float* __restrict__ C = (L == 0) ? g_l0 : g_l1;

    extern __shared__ char smem[];
    uint32_t sb = smem_u32(smem);
    int tid = threadIdx.x, wid = tid >> 5, lane = tid & 31;
    int base = blockIdx.x * 128;

    // ---- stage A once
    if (L == 0) {
        // load fp32 x, split to bf16 hi/lo in registers (fused split)
        for (int idx = tid; idx < 128 * 32; idx += 256) {
            int row = idx >> 5, q = idx & 31;
            int gr = base + row;
            float4 v = make_float4(0.f, 0.f, 0.f, 0.f);
            if (gr < M) v = *(const float4*)(xsrc + (size_t)gr * 128 + q * 4);
            __nv_bfloat16 hx = __float2bfloat16_rn(v.x), hy = __float2bfloat16_rn(v.y);
            __nv_bfloat16 hz = __float2bfloat16_rn(v.z), hw = __float2bfloat16_rn(v.w);
            __nv_bfloat16 lx = __float2bfloat16_rn(v.x - __bfloat162float(hx));
            __nv_bfloat16 ly = __float2bfloat16_rn(v.y - __bfloat162float(hy));
            __nv_bfloat16 lz = __float2bfloat16_rn(v.z - __bfloat162float(hz));
            __nv_bfloat16 lw = __float2bfloat16_rn(v.w - __bfloat162float(hw));
            __nv_bfloat162 h01(hx, hy), h23(hz, hw), l01(lx, ly), l23(lz, lw);
            uint2 uh, ul;
            uh.x = *reinterpret_cast<uint32_t*>(&h01); uh.y = *reinterpret_cast<uint32_t*>(&h23);
            ul.x = *reinterpret_cast<uint32_t*>(&l01); ul.y = *reinterpret_cast<uint32_t*>(&l23);
            *(uint2*)(smem + SM_AHI + row * PB + q * 8) = uh;
            *(uint2*)(smem + SM_ALO + row * PB + q * 8) = ul;
        }
    } else {
        // bf16 hi/lo already materialized by k_agg0 (padded rows are zero)
        for (int idx = tid; idx < 128 * 16; idx += 256) {
            int row = idx >> 4, q = idx & 15;
            *(uint4*)(smem + SM_AHI + row * PB + q * 16) = *(const uint4*)(g_hh + (size_t)(base + row) * 128 + q * 8);
            *(uint4*)(smem + SM_ALO + row * PB + q * 16) = *(const uint4*)(g_hl + (size_t)(base + row) * 128 + q * 8);
        }
    }

    int wm = (wid / WNN) * WARP_M;
    int wn = (wid % WNN) * 32;

    uint32_t a_off = (uint32_t)((wm + (lane & 15)) * PB + (lane >> 4) * 16);
    uint32_t b_off = (uint32_t)((wn + (lane & 7)) * PB + (((lane & 15) >> 3)) * 16);

#pragma unroll
    for (int slab = 0; slab < NSLAB; slab++) {
        int noff = slab * NN;
        // ---- stage B slab (bf16 hi/lo)
        for (int idx = tid; idx < NN * 16; idx += 256) {
            int row = idx >> 4, q = idx & 15;
            *(uint4*)(smem + SM_BHI + row * PB + q * 16) = *(const uint4*)(Bh + (size_t)(noff + row) * 128 + q * 8);
            *(uint4*)(smem + SM_BLO + row * PB + q * 16) = *(const uint4*)(Bl + (size_t)(noff + row) * 128 + q * 8);
        }
        __syncthreads();

        float acc[MI][NI][4];
#pragma unroll
        for (int mi = 0; mi < MI; mi++)
#pragma unroll
            for (int ni = 0; ni < NI; ni++)
#pragma unroll
                for (int r = 0; r < 4; r++) acc[mi][ni][r] = 0.f;

#pragma unroll
        for (int p = 0; p < 3; p++) {
            uint32_t abase = sb + ((p == 1) ? SM_ALO : SM_AHI) + a_off;
            uint32_t bbase = sb + ((p == 2) ? SM_BLO : SM_BHI) + b_off;
#pragma unroll
            for (int ks = 0; ks < 8; ks++) {
                uint32_t a[MI][4], b[NI][2];
#pragma unroll
                for (int mi = 0; mi < MI; mi++)
                    ldsm_x4(a[mi], abase + mi * 16 * PB + ks * 32);
#pragma unroll
                for (int ni = 0; ni < NI; ni++)
                    ldsm_x2(b[ni], bbase + ni * 8 * PB + ks * 32);
#pragma unroll
                for (int mi = 0; mi < MI; mi++)
#pragma unroll
                    for (int ni = 0; ni < NI; ni++)
                        mma_bf16(acc[mi][ni], a[mi], b[ni]);
            }
        }

        // ---- C store: d0,d1 -> (row g, col tg*2..+1); d2,d3 -> row g+8
        int g = lane >> 2, tg = lane & 3;
#pragma unroll
        for (int mi = 0; mi < MI; mi++) {
            int r0 = base + wm + mi * 16 + g;
#pragma unroll
            for (int ni = 0; ni < NI; ni++) {
                int col = noff + wn + ni * 8 + tg * 2;
                *(float2*)(C + (size_t)r0 * CS + col)       = make_float2(acc[mi][ni][0], acc[mi][ni][1]);
                *(float2*)(C + (size_t)(r0 + 8) * CS + col) = make_float2(acc[mi][ni][2], acc[mi][ni][3]);
            }
        }

        // ---- fused attention logits (h-columns: slab 0 only)
        int head = wid % WNN;
        if (slab == 0 && !(L == 1 && head != 0)) {
            float s_w[NI * 2], d_w[NI * 2];
#pragma unroll
            for (int ni = 0; ni < NI; ni++) {
                int ci = ni * 8 + tg * 2;
                s_w[ni * 2]     = __ldg(attS + head * 32 + ci);
                s_w[ni * 2 + 1] = __ldg(attS + head * 32 + ci + 1);
                d_w[ni * 2]     = __ldg(attD + head * 32 + ci);
                d_w[ni * 2 + 1] = __ldg(attD + head * 32 + ci + 1);
            }
#pragma unroll
            for (int mi = 0; mi < MI; mi++) {
                float s0 = 0.f, d0 = 0.f, s1 = 0.f, d1 = 0.f;
#pragma unroll
                for (int ni = 0; ni < NI; ni++) {
                    s0 = fmaf(acc[mi][ni][0], s_w[ni * 2], fmaf(acc[mi][ni][1], s_w[ni * 2 + 1], s0));
                    d0 = fmaf(acc[mi][ni][0], d_w[ni * 2], fmaf(acc[mi][ni][1], d_w[ni * 2 + 1], d0));
                    s1 = fmaf(acc[mi][ni][2], s_w[ni * 2], fmaf(acc[mi][ni][3], s_w[ni * 2 + 1], s1));
                    d1 = fmaf(acc[mi][ni][2], d_w[ni * 2], fmaf(acc[mi][ni][3], d_w[ni * 2 + 1], d1));
                }
#pragma unroll
                for (int o = 1; o <= 2; o <<= 1) {
                    s0 += __shfl_xor_sync(0xffffffffu, s0, o);
                    d0 += __shfl_xor_sync(0xffffffffu, d0, o);
                    s1 += __shfl_xor_sync(0xffffffffu, s1, o);
                    d1 += __shfl_xor_sync(0xffffffffu, d1, o);
                }
                if (tg == 0) {
                    int r0 = base + wm + mi * 16 + g;
                    int r1 = r0 + 8;
                    if (L == 0) {
                        if (r0 < M) { g_as0[r0 * 4 + head] = s0; g_ad0[r0 * 4 + head] = d0; }
                        if (r1 < M) { g_as0[r1 * 4 + head] = s1; g_ad0[r1 * 4 + head] = d1; }
                    } else {
                        if (r0 < M) { g_as1[r0] = s0; g_ad1[r0] = d0; }
                        if (r1 < M) { g_as1[r1] = s1; g_ad1[r1] = d1; }
                    }
                }
            }
        }
        if (slab + 1 < NSLAB) __syncthreads();   // protect B restage
    }
}

// ---------------- layer-0 aggregation: warp per dst node --------------------
// Weight phase unchanged (lane covers (edge, head=lane&3)). Gather phase
// remapped: lane owns cols lane*4..lane*4+3 (all in head lane>>3), so each
// edge costs ONE LDG.128 + one scalar LDS broadcast + 4 FMAs.
__global__ void k_agg0(const float* __restrict__ bias0, const float* __restrict__ linb0, int n) {
    __shared__ float sw[8][32][4];
    __shared__ int   ss[8][32];
    int gw = (blockIdx.x * blockDim.x + threadIdx.x) >> 5;
    int warp = threadIdx.x >> 5;
    int lane = threadIdx.x & 31;
    if (gw >= n) return;
    int beg = g_rowptr[gw], end = g_rowptr[gw + 1];

    int   hsel = lane & 3;       // weight-phase head
    int   hq   = lane >> 3;      // gather-phase head (cols lane*4..+3)
    float4 ad4 = *(const float4*)(g_ad0 + gw * 4);
    float adh = (hsel == 0) ? ad4.x : (hsel == 1) ? ad4.y : (hsel == 2) ? ad4.z : ad4.w;

    float dn = 0.f;
    float acc0 = 0.f, acc1 = 0.f, acc2 = 0.f, acc3 = 0.f;

    for (int cbeg = beg; cbeg < end; cbeg += 32) {
        int cnt = min(32, end - cbeg);
#pragma unroll
        for (int c = 0; c < 4; c++) {
            int ei = c * 8 + (lane >> 2);
            float w = 0.f;
            if (ei < cnt) {
                int s = g_csr_src[cbeg + ei];
                if (hsel == 0) ss[warp][ei] = s;
                float ev = g_as0[s * 4 + hsel] + adh;
                ev = ev > 0.f ? ev : 0.2f * ev;
                w = __expf(ev);
            }
            sw[warp][ei][hsel] = w;
            dn += w;
        }
        __syncwarp();
#pragma unroll 4
        for (int e2 = 0; e2 < cnt; e2++) {
            float w = sw[warp][e2][hq];
            int s = ss[warp][e2];
            float4 v = *(const float4*)(g_l0 + (size_t)s * 256 + lane * 4);
            acc0 = fmaf(w, v.x, acc0);
            acc1 = fmaf(w, v.y, acc1);
            acc2 = fmaf(w, v.z, acc2);
            acc3 = fmaf(w, v.w, acc3);
        }
        __syncwarp();
    }

#pragma unroll
    for (int o = 4; o <= 16; o <<= 1) dn += __shfl_xor_sync(0xffffffffu, dn, o);
    float invh = 1.f / (dn + 1e-16f);
    // lane hq (hq<4) holds the denominator for head hq (its hsel == hq)
    float invsel = __shfl_sync(0xffffffffu, invh, hq);

    float4 b4  = *(const float4*)(bias0 + lane * 4);
    float4 lb4 = *(const float4*)(linb0 + lane * 4);
    float4 sk  = *(const float4*)(g_l0 + (size_t)gw * 256 + 128 + lane * 4);
    float o0 = acc0 * invsel + b4.x + lb4.x + sk.x;
    float o1 = acc1 * invsel + b4.y + lb4.y + sk.y;
    float o2 = acc2 * invsel + b4.z + lb4.z + sk.z;
    float o3 = acc3 * invsel + b4.w + lb4.w + sk.w;
    o0 = o0 > 0.f ? o0 : (__expf(o0) - 1.f);
    o1 = o1 > 0.f ? o1 : (__expf(o1) - 1.f);
    o2 = o2 > 0.f ? o2 : (__expf(o2) - 1.f);
    o3 = o3 > 0.f ? o3 : (__expf(o3) - 1.f);

    // store h as bf16 hi/lo: cols lane*4..+3 contiguous (8B stores)
    size_t cb = (size_t)gw * 128 + lane * 4;
    __nv_bfloat16 h0 = __float2bfloat16_rn(o0), h1 = __float2bfloat16_rn(o1);
    __nv_bfloat16 h2 = __float2bfloat16_rn(o2), h3 = __float2bfloat16_rn(o3);
    __nv_bfloat162 hh01(h0, h1), hh23(h2, h3);
    __nv_bfloat162 ll01(__float2bfloat16_rn(o0 - __bfloat162float(h0)),
                        __float2bfloat16_rn(o1 - __bfloat162float(h1)));
    __nv_bfloat162 ll23(__float2bfloat16_rn(o2 - __bfloat162float(h2)),
                        __float2bfloat16_rn(o3 - __bfloat162float(h3)));
    uint2 uh, ul;
    uh.x = *reinterpret_cast<uint32_t*>(&hh01); uh.y = *reinterpret_cast<uint32_t*>(&hh23);
    ul.x = *reinterpret_cast<uint32_t*>(&ll01); ul.y = *reinterpret_cast<uint32_t*>(&ll23);
    *(uint2*)(g_hh + cb) = uh;
    *(uint2*)(g_hl + cb) = ul;
}

// ---------------- layer-1 aggregation: warp per dst node --------------------
__global__ void k_agg1(const float* __restrict__ bias1, const float* __restrict__ linb1,
                       float* __restrict__ out, int n) {
    __shared__ float sw1[8][32];
    __shared__ int   ss1[8][32];
    int gw = (blockIdx.x * blockDim.x + threadIdx.x) >> 5;
    int warp = threadIdx.x >> 5;
    int lane = threadIdx.x & 31;
    if (gw >= n) return;
    int beg = g_rowptr[gw], end = g_rowptr[gw + 1];
    float ad = g_ad1[gw];

    float dn = 0.f;
    float acc = 0.f;
    for (int cbeg = beg; cbeg < end; cbeg += 32) {
        int cnt = min(32, end - cbeg);
        float w = 0.f;
        if (lane < cnt) {
            int s = g_csr_src[cbeg + lane];
            ss1[warp][lane] = s;
            float ev = g_as1[s] + ad;
            ev = ev > 0.f ? ev : 0.2f * ev;
            w = __expf(ev);
        }
        sw1[warp][lane] = w;
        dn += w;
        __syncwarp();
#pragma unroll 2
        for (int e2 = 0; e2 < cnt; e2++) {
            int s = ss1[warp][e2];
            acc = fmaf(sw1[warp][e2], g_l1[(size_t)s * 64 + lane], acc);
        }
        __syncwarp();
    }
#pragma unroll
    for (int o = 16; o; o >>= 1) dn += __shfl_xor_sync(0xffffffffu, dn, o);
    float inv = 1.f / (dn + 1e-16f);

    out[(size_t)gw * 32 + lane] =
        acc * inv + bias1[lane] + linb1[lane] + g_l1[(size_t)gw * 64 + 32 + lane];
}

// ---------------- launcher ---------------------------------------------------
extern "C" void kernel_launch(void* const* d_in, const int* in_sizes, int n_in,
                              void* d_out, int out_size) {
    const float* x   = (const float*)d_in[0];
    const int*   ei  = (const int*)  d_in[1];
    const float* W0  = (const float*)d_in[2];
    const float* as0 = (const float*)d_in[3];
    const float* ad0 = (const float*)d_in[4];
    const float* b0  = (const float*)d_in[5];
    const float* lW0 = (const float*)d_in[6];
    const float* lb0 = (const float*)d_in[7];
    const float* W1  = (const float*)d_in[8];
    const float* as1 = (const float*)d_in[9];
    const float* ad1 = (const float*)d_in[10];
    const float* b1  = (const float*)d_in[11];
    const float* lW1 = (const float*)d_in[12];
    const float* lb1 = (const float*)d_in[13];
    float* out = (float*)d_out;

    int n = in_sizes[0] / 128;
    int e = in_sizes[1] / 2;
    int etot = n + e;
    int nb = (n + SCAN_BS - 1) / SCAN_BS;
    int ntiles = (n + 127) / 128;

    const int smem0 = 2 * 128 * 272 + 2 * 128 * 272;  // 139264
    const int smem1 = 2 * 128 * 272 + 2 * 64 * 272;   // 104448
    static bool inited = false;
    static cudaStream_t s2;
    static cudaEvent_t evFork, evCsr;
    if (!inited) {
        cudaFuncSetAttribute(k_mma<0>, cudaFuncAttributeMaxDynamicSharedMemorySize, smem0);
        cudaFuncSetAttribute(k_mma<1>, cudaFuncAttributeMaxDynamicSharedMemorySize, smem1);
        cudaStreamCreateWithFlags(&s2, cudaStreamNonBlocking);
        cudaEventCreateWithFlags(&evFork, cudaEventDisableTiming);
        cudaEventCreateWithFlags(&evCsr, cudaEventDisableTiming);
        inited = true;
    }

    // default stream: weight split first (in flight during fork bookkeeping)
    k_setupW<<<(128 * 128 + 255) / 256, 256>>>(W0, lW0, W1, lW1);

    // fork: CSR chain on s2, concurrent with weight split + GEMM0
    cudaEventRecord(evFork, 0);
    cudaStreamWaitEvent(s2, evFork, 0);

    k_zero_deg<<<(n + 255) / 256, 256, 0, s2>>>(n);
    k_hist<<<(etot + 255) / 256, 256, 0, s2>>>(ei, e, etot);
    k_scan1<<<nb, SCAN_BS, 0, s2>>>(n);
    k_scan23<<<(n + 255) / 256, 256, 0, s2>>>(n);
    k_scatter<<<(etot + 255) / 256, 256, 0, s2>>>(ei, e, etot);
    cudaEventRecord(evCsr, s2);

    // default stream: layer-0 GEMM (fused x split + logits)
    k_mma<0><<<ntiles, 256, smem0>>>(x, as0, ad0, n);

    // join: aggregation needs CSR
    cudaStreamWaitEvent(0, evCsr, 0);
    k_agg0<<<(n + 7) / 8, 256>>>(b0, lb0, n);

    // layer 1
    k_mma<1><<<ntiles, 256, smem1>>>(x, as1, ad1, n);
    k_agg1<<<(n + 7) / 8, 256>>>(b1, lb1, out, n);
}

// round 17
// speedup vs baseline: 1.0469x; 1.0469x over previous
#include <cuda_runtime.h>
#include <cuda_bf16.h>
#include <cuda_fp16.h>
#include <cstdint>

// ---------------- problem-size constants (fixed by the reference) ----------
#define NNODES   50000
#define NPAD     50048                  // padded to multiple of 128
#define NEDGES   800000
#define ETOT     (NNODES + NEDGES)      // 850000 (edges + self loops)
#define SCAN_BS  512

// ---------------- device scratch (no allocations allowed) ------------------
// ONLY referenced from device code (host-side use of a __device__ symbol as a
// kernel arg silently reads the host shadow via ATS -> zero output).
__device__ float g_l0[(size_t)NPAD * 256];   // only cols 128..255 (skip) written
__device__ float g_l1[(size_t)NPAD * 64];    // only cols 32..63 (skip) written
__device__ __half g_c0f[(size_t)NPAD * 128]; // conv0 output, fp16 [row][col]
__device__ __half g_c1f[(size_t)NPAD * 32];  // conv1 output, fp16 [row][col]
__device__ __nv_bfloat16 g_hh[(size_t)NPAD * 128];
__device__ __nv_bfloat16 g_hl[(size_t)NPAD * 128];
__device__ float g_as0[NNODES * 4];
__device__ float g_ad0[NNODES * 4];
__device__ float g_as1[NNODES];
__device__ float g_ad1[NNODES];
__device__ int   g_deg[NNODES + 64];
__device__ int   g_rowtmp[NNODES + 64];
__device__ int   g_rowptr[NNODES + 64];
__device__ int   g_cursor[NNODES + 64];
__device__ int   g_csr_src[ETOT + 64];
__device__ int   g_bsum[SCAN_BS];
__device__ __nv_bfloat16 g_B0h[256 * 128];
__device__ __nv_bfloat16 g_B0l[256 * 128];
__device__ __nv_bfloat16 g_B1h[64 * 128];
__device__ __nv_bfloat16 g_B1l[64 * 128];

// ---------------- helpers ---------------------------------------------------
__device__ __forceinline__ uint32_t smem_u32(const void* p) {
    uint32_t a;
    asm("{ .reg .u64 t; cvta.to.shared.u64 t, %1; cvt.u32.u64 %0, t; }" : "=r"(a) : "l"(p));
    return a;
}
__device__ __forceinline__ void ldsm_x4(uint32_t* r, uint32_t addr) {
    asm volatile("ldmatrix.sync.aligned.m8n8.x4.shared.b16 {%0,%1,%2,%3}, [%4];"
                 : "=r"(r[0]), "=r"(r[1]), "=r"(r[2]), "=r"(r[3]) : "r"(addr));
}
__device__ __forceinline__ void ldsm_x2(uint32_t* r, uint32_t addr) {
    asm volatile("ldmatrix.sync.aligned.m8n8.x2.shared.b16 {%0,%1}, [%2];"
                 : "=r"(r[0]), "=r"(r[1]) : "r"(addr));
}
__device__ __forceinline__ void mma_bf16(float* d, const uint32_t* a, const uint32_t* b) {
    asm volatile(
        "mma.sync.aligned.m16n8k16.row.col.f32.bf16.bf16.f32 "
        "{%0,%1,%2,%3}, {%4,%5,%6,%7}, {%8,%9}, {%0,%1,%2,%3};"
        : "+f"(d[0]), "+f"(d[1]), "+f"(d[2]), "+f"(d[3])
        : "r"(a[0]), "r"(a[1]), "r"(a[2]), "r"(a[3]), "r"(b[0]), "r"(b[1]));
}

// ---------------- setup: weight split (default stream, feeds GEMM0) ---------
__global__ void k_setupW(const float* __restrict__ W0, const float* __restrict__ lW0,
                         const float* __restrict__ W1, const float* __restrict__ lW1) {
    int i = blockIdx.x * blockDim.x + threadIdx.x;
    if (i < 128 * 128) {
        float v = W0[i];
        __nv_bfloat16 h = __float2bfloat16_rn(v);
        g_B0h[i] = h; g_B0l[i] = __float2bfloat16_rn(v - __bfloat162float(h));
        v = lW0[i];
        h = __float2bfloat16_rn(v);
        g_B0h[128 * 128 + i] = h; g_B0l[128 * 128 + i] = __float2bfloat16_rn(v - __bfloat162float(h));
    }
    if (i < 32 * 128) {
        float v = W1[i];
        __nv_bfloat16 h = __float2bfloat16_rn(v);
        g_B1h[i] = h; g_B1l[i] = __float2bfloat16_rn(v - __bfloat162float(h));
        v = lW1[i];
        h = __float2bfloat16_rn(v);
        g_B1h[32 * 128 + i] = h; g_B1l[32 * 128 + i] = __float2bfloat16_rn(v - __bfloat162float(h));
    }
}

// ---------------- CSR build (stream s2) --------------------------------------
__global__ void k_zero_deg(int n) {
    int i = blockIdx.x * blockDim.x + threadIdx.x;
    if (i < n) g_deg[i] = 0;
}
__global__ void k_hist(const int* __restrict__ ei, int e, int etot) {
    int k = blockIdx.x * blockDim.x + threadIdx.x;
    if (k >= etot) return;
    int dst = (k < e) ? ei[e + k] : (k - e);
    atomicAdd(&g_deg[dst], 1);
}
__global__ void k_scan1(int n) {
    __shared__ int sh[SCAN_BS];
    int t = threadIdx.x;
    int i = blockIdx.x * SCAN_BS + t;
    int v = (i < n) ? g_deg[i] : 0;
    sh[t] = v;
    __syncthreads();
    for (int o = 1; o < SCAN_BS; o <<= 1) {
        int x = (t >= o) ? sh[t - o] : 0;
        __syncthreads();
        sh[t] += x;
        __syncthreads();
    }
    if (i < n) g_rowtmp[i] = sh[t];
    if (t == SCAN_BS - 1) g_bsum[blockIdx.x] = sh[t];
}
// merged scan2+scan3: block b (256 thr) lies fully in bsum region b>>1, so it
// block-reduces g_bsum[0..b>>1) and applies the exclusive region offset.
__global__ void k_scan23(int n) {
    __shared__ int red[256];
    int t = threadIdx.x, b = blockIdx.x;
    int region = b >> 1;                    // 512-wide regions, 256-wide blocks
    red[t] = (t < region) ? g_bsum[t] : 0;  // region <= 98 < 256
    __syncthreads();
    for (int o = 128; o; o >>= 1) {
        if (t < o) red[t] += red[t + o];
        __syncthreads();
    }
    int pre = red[0];
    int i = b * 256 + t;
    if (i < n) {
        int incl = g_rowtmp[i] + pre;
        g_rowptr[i + 1] = incl;
        g_cursor[i] = incl - g_deg[i];
        if (i == 0) g_rowptr[0] = 0;
    }
}
__global__ void k_scatter(const int* __restrict__ ei, int e, int etot) {
    int k = blockIdx.x * blockDim.x + threadIdx.x;
    if (k >= etot) return;
    int src, dst;
    if (k < e) { src = ei[k]; dst = ei[e + k]; }
    else       { src = dst = k - e; }
    int pos = atomicAdd(&g_cursor[dst], 1);
    g_csr_src[pos] = src;
}

// ---------------- HMMA GEMM + fused attention logits -------------------------
// Single launch per layer. A staged once; B processed in NSLAB slabs of NN
// columns inside the kernel (acc registers reused).
// fp32 via 3-product bf16 split (Ah*Bh + Al*Bh + Ah*Bl), fp32 reg accum.
// L=0: A = x (fp32, split in staging), B=g_B0h/l, 2 slabs of 128:
//      slab0 (conv) -> fp16 g_c0f (dense __half2 stores) + fused logits;
//      slab1 (skip) -> fp32 g_l0 cols 128..255.
// L=1: A = g_hh/g_hl, B=g_B1h/l, 1 slab of 64:
//      cols 0-31 (conv) -> fp16 g_c1f + fused logits; cols 32-63 -> fp32 g_l1.
template <int L>
__global__ void __launch_bounds__(256) k_mma(
    const float* __restrict__ xsrc,
    const float* __restrict__ attS, const float* __restrict__ attD, int M)
{
    constexpr int NSLAB = (L == 0) ? 2 : 1;
    constexpr int NN  = (L == 0) ? 128 : 64;   // cols per slab
    constexpr int CS  = (L == 0) ? 256 : 64;   // C row stride
    constexpr int CCS = (L == 0) ? 128 : 32;   // fp16 conv row stride
    constexpr int WNN = (NN == 128) ? 4 : 2;   // warps along n
    constexpr int WMN = 8 / WNN;               // warps along m
    constexpr int WARP_M = 128 / WMN;          // 64 or 32
    constexpr int MI = WARP_M / 16;            // 4 or 2
    constexpr int NI = 4;                      // WARP_N = 32 (one head)
    constexpr int PB = 272;                    // pitch bytes (17*16B -> conflict-free)
    constexpr int SM_AHI = 0;
    constexpr int SM_ALO = 128 * PB;
    constexpr int SM_BHI = 2 * 128 * PB;
    constexpr int SM_BLO = SM_BHI + NN * PB;

    const __nv_bfloat16* __restrict__ Bh = (L == 0) ? g_B0h : g_B1h;
    const __nv_bfloat16* __restrict__ Bl = (L == 0) ? g_B0l : g_B1l;
    float* __restrict__ C  = (L == 0) ? g_l0 : g_l1;
    __half* __restrict__ Cc = (L == 0) ? g_c0f : g_c1f;

    extern __shared__ char smem[];
    uint32_t sb = smem_u32(smem);
    int tid = threadIdx.x, wid = tid >> 5, lane = tid & 31;
    int base = blockIdx.x * 128;

    // ---- stage A once
    if (L == 0) {
        // load fp32 x, split to bf16 hi/lo in registers (fused split)
        for (int idx = tid; idx < 128 * 32; idx += 256) {
            int row = idx >> 5, q = idx & 31;
            int gr = base + row;
            float4 v = make_float4(0.f, 0.f, 0.f, 0.f);
            if (gr < M) v = *(const float4*)(xsrc + (size_t)gr * 128 + q * 4);
            __nv_bfloat16 hx = __float2bfloat16_rn(v.x), hy = __float2bfloat16_rn(v.y);
            __nv_bfloat16 hz = __float2bfloat16_rn(v.z), hw = __float2bfloat16_rn(v.w);
            __nv_bfloat16 lx = __float2bfloat16_rn(v.x - __bfloat162float(hx));
            __nv_bfloat16 ly = __float2bfloat16_rn(v.y - __bfloat162float(hy));
            __nv_bfloat16 lz = __float2bfloat16_rn(v.z - __bfloat162float(hz));
            __nv_bfloat16 lw = __float2bfloat16_rn(v.w - __bfloat162float(hw));
            __nv_bfloat162 h01(hx, hy), h23(hz, hw), l01(lx, ly), l23(lz, lw);
            uint2 uh, ul;
            uh.x = *reinterpret_cast<uint32_t*>(&h01); uh.y = *reinterpret_cast<uint32_t*>(&h23);
            ul.x = *reinterpret_cast<uint32_t*>(&l01); ul.y = *reinterpret_cast<uint32_t*>(&l23);
            *(uint2*)(smem + SM_AHI + row * PB + q * 8) = uh;
            *(uint2*)(smem + SM_ALO + row * PB + q * 8) = ul;
        }
    } else {
        // bf16 hi/lo already materialized by k_agg0 (padded rows are zero)
        for (int idx = tid; idx < 128 * 16; idx += 256) {
            int row = idx >> 4, q = idx & 15;
            *(uint4*)(smem + SM_AHI + row * PB + q * 16) = *(const uint4*)(g_hh + (size_t)(base + row) * 128 + q * 8);
            *(uint4*)(smem + SM_ALO + row * PB + q * 16) = *(const uint4*)(g_hl + (size_t)(base + row) * 128 + q * 8);
        }
    }

    int wm = (wid / WNN) * WARP_M;
    int wn = (wid % WNN) * 32;

    uint32_t a_off = (uint32_t)((wm + (lane & 15)) * PB + (lane >> 4) * 16);
    uint32_t b_off = (uint32_t)((wn + (lane & 7)) * PB + (((lane & 15) >> 3)) * 16);

#pragma unroll
    for (int slab = 0; slab < NSLAB; slab++) {
        int noff = slab * NN;
        // ---- stage B slab (bf16 hi/lo)
        for (int idx = tid; idx < NN * 16; idx += 256) {
            int row = idx >> 4, q = idx & 15;
            *(uint4*)(smem + SM_BHI + row * PB + q * 16) = *(const uint4*)(Bh + (size_t)(noff + row) * 128 + q * 8);
            *(uint4*)(smem + SM_BLO + row * PB + q * 16) = *(const uint4*)(Bl + (size_t)(noff + row) * 128 + q * 8);
        }
        __syncthreads();

        float acc[MI][NI][4];
#pragma unroll
        for (int mi = 0; mi < MI; mi++)
#pragma unroll
            for (int ni = 0; ni < NI; ni++)
#pragma unroll
                for (int r = 0; r < 4; r++) acc[mi][ni][r] = 0.f;

#pragma unroll
        for (int p = 0; p < 3; p++) {
            uint32_t abase = sb + ((p == 1) ? SM_ALO : SM_AHI) + a_off;
            uint32_t bbase = sb + ((p == 2) ? SM_BLO : SM_BHI) + b_off;
#pragma unroll
            for (int ks = 0; ks < 8; ks++) {
                uint32_t a[MI][4], b[NI][2];
#pragma unroll
                for (int mi = 0; mi < MI; mi++)
                    ldsm_x4(a[mi], abase + mi * 16 * PB + ks * 32);
#pragma unroll
                for (int ni = 0; ni < NI; ni++)
                    ldsm_x2(b[ni], bbase + ni * 8 * PB + ks * 32);
#pragma unroll
                for (int mi = 0; mi < MI; mi++)
#pragma unroll
                    for (int ni = 0; ni < NI; ni++)
                        mma_bf16(acc[mi][ni], a[mi], b[ni]);
            }
        }

        // ---- stores: conv part -> fp16 (dense __half2), skip part -> fp32
        int g = lane >> 2, tg = lane & 3;
        bool conv = (L == 0) ? (slab == 0) : (wn == 0);
#pragma unroll
        for (int mi = 0; mi < MI; mi++) {
            int r0 = base + wm + mi * 16 + g;
#pragma unroll
            for (int ni = 0; ni < NI; ni++) {
                if (conv) {
                    int col = wn + ni * 8 + tg * 2;
                    __half2 p0(__float2half_rn(acc[mi][ni][0]), __float2half_rn(acc[mi][ni][1]));
                    __half2 p1(__float2half_rn(acc[mi][ni][2]), __float2half_rn(acc[mi][ni][3]));
                    *(__half2*)(Cc + (size_t)r0 * CCS + col)       = p0;
                    *(__half2*)(Cc + (size_t)(r0 + 8) * CCS + col) = p1;
                } else {
                    int col = noff + wn + ni * 8 + tg * 2;
                    *(float2*)(C + (size_t)r0 * CS + col)       = make_float2(acc[mi][ni][0], acc[mi][ni][1]);
                    *(float2*)(C + (size_t)(r0 + 8) * CS + col) = make_float2(acc[mi][ni][2], acc[mi][ni][3]);
                }
            }
        }

        // ---- fused attention logits (conv columns only)
        int head = wn >> 5;
        if (conv) {
            float s_w[NI * 2], d_w[NI * 2];
#pragma unroll
            for (int ni = 0; ni < NI; ni++) {
                int ci = ni * 8 + tg * 2;
                s_w[ni * 2]     = __ldg(attS + head * 32 + ci);
                s_w[ni * 2 + 1] = __ldg(attS + head * 32 + ci + 1);
                d_w[ni * 2]     = __ldg(attD + head * 32 + ci);
                d_w[ni * 2 + 1] = __ldg(attD + head * 32 + ci + 1);
            }
#pragma unroll
            for (int mi = 0; mi < MI; mi++) {
                float s0 = 0.f, d0 = 0.f, s1 = 0.f, d1 = 0.f;
#pragma unroll
                for (int ni = 0; ni < NI; ni++) {
                    s0 = fmaf(acc[mi][ni][0], s_w[ni * 2], fmaf(acc[mi][ni][1], s_w[ni * 2 + 1], s0));
                    d0 = fmaf(acc[mi][ni][0], d_w[ni * 2], fmaf(acc[mi][ni][1], d_w[ni * 2 + 1], d0));
                    s1 = fmaf(acc[mi][ni][2], s_w[ni * 2], fmaf(acc[mi][ni][3], s_w[ni * 2 + 1], s1));
                    d1 = fmaf(acc[mi][ni][2], d_w[ni * 2], fmaf(acc[mi][ni][3], d_w[ni * 2 + 1], d1));
                }
#pragma unroll
                for (int o = 1; o <= 2; o <<= 1) {
                    s0 += __shfl_xor_sync(0xffffffffu, s0, o);
                    d0 += __shfl_xor_sync(0xffffffffu, d0, o);
                    s1 += __shfl_xor_sync(0xffffffffu, s1, o);
                    d1 += __shfl_xor_sync(0xffffffffu, d1, o);
                }
                if (tg == 0) {
                    int r0 = base + wm + mi * 16 + g;
                    int r1 = r0 + 8;
                    if (L == 0) {
                        if (r0 < M) { g_as0[r0 * 4 + head] = s0; g_ad0[r0 * 4 + head] = d0; }
                        if (r1 < M) { g_as0[r1 * 4 + head] = s1; g_ad0[r1 * 4 + head] = d1; }
                    } else {
                        if (r0 < M) { g_as1[r0] = s0; g_ad1[r0] = d0; }
                        if (r1 < M) { g_as1[r1] = s1; g_ad1[r1] = d1; }
                    }
                }
            }
        }
        if (slab + 1 < NSLAB) __syncthreads();   // protect B restage
    }
}

// ---------------- layer-0 aggregation: warp per dst node --------------------
// Weight phase: lane covers (edge, head=lane&3). Gather phase: lane owns cols
// lane*4..+3 (head lane>>3) -> ONE LDG.64 (4 fp16) + scalar LDS + 4 FMAs/edge.
__global__ void k_agg0(const float* __restrict__ bias0, const float* __restrict__ linb0, int n) {
    __shared__ float sw[8][32][4];
    __shared__ int   ss[8][32];
    int gw = (blockIdx.x * blockDim.x + threadIdx.x) >> 5;
    int warp = threadIdx.x >> 5;
    int lane = threadIdx.x & 31;
    if (gw >= n) return;
    int beg = g_rowptr[gw], end = g_rowptr[gw + 1];

    int   hsel = lane & 3;       // weight-phase head
    int   hq   = lane >> 3;      // gather-phase head (cols lane*4..+3)
    float4 ad4 = *(const float4*)(g_ad0 + gw * 4);
    float adh = (hsel == 0) ? ad4.x : (hsel == 1) ? ad4.y : (hsel == 2) ? ad4.z : ad4.w;

    float dn = 0.f;
    float acc0 = 0.f, acc1 = 0.f, acc2 = 0.f, acc3 = 0.f;

    for (int cbeg = beg; cbeg < end; cbeg += 32) {
        int cnt = min(32, end - cbeg);
#pragma unroll
        for (int c = 0; c < 4; c++) {
            int ei = c * 8 + (lane >> 2);
            float w = 0.f;
            if (ei < cnt) {
                int s = g_csr_src[cbeg + ei];
                if (hsel == 0) ss[warp][ei] = s;
                float ev = g_as0[s * 4 + hsel] + adh;
                ev = ev > 0.f ? ev : 0.2f * ev;
                w = __expf(ev);
            }
            sw[warp][ei][hsel] = w;
            dn += w;
        }
        __syncwarp();
#pragma unroll 4
        for (int e2 = 0; e2 < cnt; e2++) {
            float w = sw[warp][e2][hq];
            int s = ss[warp][e2];
            uint2 u = *(const uint2*)(g_c0f + (size_t)s * 128 + lane * 4);
            __half2 p01 = *reinterpret_cast<__half2*>(&u.x);
            __half2 p23 = *reinterpret_cast<__half2*>(&u.y);
            float2 f01 = __half22float2(p01);
            float2 f23 = __half22float2(p23);
            acc0 = fmaf(w, f01.x, acc0);
            acc1 = fmaf(w, f01.y, acc1);
            acc2 = fmaf(w, f23.x, acc2);
            acc3 = fmaf(w, f23.y, acc3);
        }
        __syncwarp();
    }

#pragma unroll
    for (int o = 4; o <= 16; o <<= 1) dn += __shfl_xor_sync(0xffffffffu, dn, o);
    float invh = 1.f / (dn + 1e-16f);
    // lane hq (hq<4) holds the denominator for head hq (its hsel == hq)
    float invsel = __shfl_sync(0xffffffffu, invh, hq);

    float4 b4  = *(const float4*)(bias0 + lane * 4);
    float4 lb4 = *(const float4*)(linb0 + lane * 4);
    float4 sk  = *(const float4*)(g_l0 + (size_t)gw * 256 + 128 + lane * 4);
    float o0 = acc0 * invsel + b4.x + lb4.x + sk.x;
    float o1 = acc1 * invsel + b4.y + lb4.y + sk.y;
    float o2 = acc2 * invsel + b4.z + lb4.z + sk.z;
    float o3 = acc3 * invsel + b4.w + lb4.w + sk.w;
    o0 = o0 > 0.f ? o0 : (__expf(o0) - 1.f);
    o1 = o1 > 0.f ? o1 : (__expf(o1) - 1.f);
    o2 = o2 > 0.f ? o2 : (__expf(o2) - 1.f);
    o3 = o3 > 0.f ? o3 : (__expf(o3) - 1.f);

    // store h as bf16 hi/lo: cols lane*4..+3 contiguous (8B stores)
    size_t cb = (size_t)gw * 128 + lane * 4;
    __nv_bfloat16 h0 = __float2bfloat16_rn(o0), h1 = __float2bfloat16_rn(o1);
    __nv_bfloat16 h2 = __float2bfloat16_rn(o2), h3 = __float2bfloat16_rn(o3);
    __nv_bfloat162 hh01(h0, h1), hh23(h2, h3);
    __nv_bfloat162 ll01(__float2bfloat16_rn(o0 - __bfloat162float(h0)),
                        __float2bfloat16_rn(o1 - __bfloat162float(h1)));
    __nv_bfloat162 ll23(__float2bfloat16_rn(o2 - __bfloat162float(h2)),
                        __float2bfloat16_rn(o3 - __bfloat162float(h3)));
    uint2 uh, ul;
    uh.x = *reinterpret_cast<uint32_t*>(&hh01); uh.y = *reinterpret_cast<uint32_t*>(&hh23);
    ul.x = *reinterpret_cast<uint32_t*>(&ll01); ul.y = *reinterpret_cast<uint32_t*>(&ll23);
    *(uint2*)(g_hh + cb) = uh;
    *(uint2*)(g_hl + cb) = ul;
}

// ---------------- layer-1 aggregation: warp per dst node --------------------
__global__ void k_agg1(const float* __restrict__ bias1, const float* __restrict__ linb1,
                       float* __restrict__ out, int n) {
    __shared__ float sw1[8][32];
    __shared__ int   ss1[8][32];
    int gw = (blockIdx.x * blockDim.x + threadIdx.x) >> 5;
    int warp = threadIdx.x >> 5;
    int lane = threadIdx.x & 31;
    if (gw >= n) return;
    int beg = g_rowptr[gw], end = g_rowptr[gw + 1];
    float ad = g_ad1[gw];

    float dn = 0.f;
    float acc = 0.f;
    for (int cbeg = beg; cbeg < end; cbeg += 32) {
        int cnt = min(32, end - cbeg);
        float w = 0.f;
        if (lane < cnt) {
            int s = g_csr_src[cbeg + lane];
            ss1[warp][lane] = s;
            float ev = g_as1[s] + ad;
            ev = ev > 0.f ? ev : 0.2f * ev;
            w = __expf(ev);
        }
        sw1[warp][lane] = w;
        dn += w;
        __syncwarp();
#pragma unroll 2
        for (int e2 = 0; e2 < cnt; e2++) {
            int s = ss1[warp][e2];
            acc = fmaf(sw1[warp][e2], __half2float(g_c1f[(size_t)s * 32 + lane]), acc);
        }
        __syncwarp();
    }
#pragma unroll
    for (int o = 16; o; o >>= 1) dn += __shfl_xor_sync(0xffffffffu, dn, o);
    float inv = 1.f / (dn + 1e-16f);

    out[(size_t)gw * 32 + lane] =
        acc * inv + bias1[lane] + linb1[lane] + g_l1[(size_t)gw * 64 + 32 + lane];
}

// ---------------- launcher ---------------------------------------------------
extern "C" void kernel_launch(void* const* d_in, const int* in_sizes, int n_in,
                              void* d_out, int out_size) {
    const float* x   = (const float*)d_in[0];
    const int*   ei  = (const int*)  d_in[1];
    const float* W0  = (const float*)d_in[2];
    const float* as0 = (const float*)d_in[3];
    const float* ad0 = (const float*)d_in[4];
    const float* b0  = (const float*)d_in[5];
    const float* lW0 = (const float*)d_in[6];
    const float* lb0 = (const float*)d_in[7];
    const float* W1  = (const float*)d_in[8];
    const float* as1 = (const float*)d_in[9];
    const float* ad1 = (const float*)d_in[10];
    const float* b1  = (const float*)d_in[11];
    const float* lW1 = (const float*)d_in[12];
    const float* lb1 = (const float*)d_in[13];
    float* out = (float*)d_out;

    int n = in_sizes[0] / 128;
    int e = in_sizes[1] / 2;
    int etot = n + e;
    int nb = (n + SCAN_BS - 1) / SCAN_BS;
    int ntiles = (n + 127) / 128;

    const int smem0 = 2 * 128 * 272 + 2 * 128 * 272;  // 139264
    const int smem1 = 2 * 128 * 272 + 2 * 64 * 272;   // 104448
    static bool inited = false;
    static cudaStream_t s2;
    static cudaEvent_t evFork, evCsr;
    if (!inited) {
        cudaFuncSetAttribute(k_mma<0>, cudaFuncAttributeMaxDynamicSharedMemorySize, smem0);
        cudaFuncSetAttribute(k_mma<1>, cudaFuncAttributeMaxDynamicSharedMemorySize, smem1);
        cudaStreamCreateWithFlags(&s2, cudaStreamNonBlocking);
        cudaEventCreateWithFlags(&evFork, cudaEventDisableTiming);
        cudaEventCreateWithFlags(&evCsr, cudaEventDisableTiming);
        inited = true;
    }

    // default stream: weight split first (in flight during fork bookkeeping)
    k_setupW<<<(128 * 128 + 255) / 256, 256>>>(W0, lW0, W1, lW1);

    // fork: CSR chain on s2, concurrent with weight split + GEMM0
    cudaEventRecord(evFork, 0);
    cudaStreamWaitEvent(s2, evFork, 0);

    k_zero_deg<<<(n + 255) / 256, 256, 0, s2>>>(n);
    k_hist<<<(etot + 255) / 256, 256, 0, s2>>>(ei, e, etot);
    k_scan1<<<nb, SCAN_BS, 0, s2>>>(n);
    k_scan23<<<(n + 255) / 256, 256, 0, s2>>>(n);
    k_scatter<<<(etot + 255) / 256, 256, 0, s2>>>(ei, e, etot);
    cudaEventRecord(evCsr, s2);

    // default stream: layer-0 GEMM (fused x split + logits)
    k_mma<0><<<ntiles, 256, smem0>>>(x, as0, ad0, n);

    // join: aggregation needs CSR
    cudaStreamWaitEvent(0, evCsr, 0);
    k_agg0<<<(n + 7) / 8, 256>>>(b0, lb0, n);

    // layer 1
    k_mma<1><<<ntiles, 256, smem1>>>(x, as1, ad1, n);
    k_agg1<<<(n + 7) / 8, 256>>>(b1, lb1, out, n);
}